// round 16
// baseline (speedup 1.0000x reference)
#include <cuda_runtime.h>
#include <cuda_fp16.h>
#include <float.h>
#include <stdint.h>

#define NPTS   65536
#define BGRAPH 64
#define PPG    1024

// ---------------- scratch (device globals; no allocation) ----------------
__device__ int      g_knn[NPTS * 8];          // 6 real + 2 pad (dup of nn0)
__device__ __half   g_abA[NPTS * 128];        // fp16: a (+b1) cols 0..63, b cols 64..127
__device__ __half   g_abB[NPTS * 128];        // fp16 double buffer (layer-3 input)
__device__ float4   g_pos4[NPTS];             // packed positions (x,y,z,0)
__device__ uint32_t g_pool[BGRAPH * 64];      // per-graph channel max (uint-ordered floats >= 0)
__device__ __align__(16) __half g_w2s[3][4096];  // [layer] swizzled fp16 W2^T [n=64][k=64]
__device__ __align__(16) __half g_w1s[2][8192];  // [layer] swizzled fp16 W1ab^T [n=128][k=64]

// ---------------- helpers (base-ISA: ldmatrix + mma.sync, sm_80+) ----------------
__device__ __forceinline__ uint32_t smem_u32(const void* p) {
    uint32_t a;
    asm("{ .reg .u64 t; cvta.to.shared.u64 t, %1; cvt.u32.u64 %0, t; }" : "=r"(a) : "l"(p));
    return a;
}
__device__ __forceinline__ uint32_t sw128(uint32_t off) { return off ^ ((off >> 3) & 0x70); }
__device__ __forceinline__ uint32_t pack_h2(float a, float b) {
    __half2 h = __floats2half2_rn(a, b);
    return *reinterpret_cast<uint32_t*>(&h);
}
__device__ __forceinline__ void ldsm_x4(uint32_t* r, uint32_t addr) {
    asm volatile("ldmatrix.sync.aligned.m8n8.x4.shared.b16 {%0,%1,%2,%3}, [%4];"
                 : "=r"(r[0]), "=r"(r[1]), "=r"(r[2]), "=r"(r[3]) : "r"(addr));
}
__device__ __forceinline__ void mma_16816(float* d, const uint32_t* a, const uint32_t* b) {
    asm volatile("mma.sync.aligned.m16n8k16.row.col.f32.f16.f16.f32 "
                 "{%0,%1,%2,%3}, {%4,%5,%6,%7}, {%8,%9}, {%0,%1,%2,%3};"
                 : "+f"(d[0]), "+f"(d[1]), "+f"(d[2]), "+f"(d[3])
                 : "r"(a[0]), "r"(a[1]), "r"(a[2]), "r"(a[3]), "r"(b[0]), "r"(b[1]));
}

// ---------------- kNN (k=6, 2 queries/thread, 4 blocks/graph; matches jax top_k ties) ----------------
__global__ __launch_bounds__(128) void knn_kernel(const float* __restrict__ pos)
{
    __shared__ float4 cand[128];
    int graph = blockIdx.x >> 2;
    int q0 = graph * PPG + ((blockIdx.x & 3) << 8) + threadIdx.x;
    int q1 = q0 + 128;
    float ax = pos[3*q0], ay = pos[3*q0+1], az = pos[3*q0+2];
    float bx = pos[3*q1], by = pos[3*q1+1], bz = pos[3*q1+2];
    float as = ax*ax + ay*ay + az*az;
    float bs = bx*bx + by*by + bz*bz;
    g_pos4[q0] = make_float4(ax, ay, az, 0.f);
    g_pos4[q1] = make_float4(bx, by, bz, 0.f);
    float ad[6], bd[6]; int ai[6], bi[6];
#pragma unroll
    for (int t = 0; t < 6; t++) { ad[t] = FLT_MAX; ai[t] = 0; bd[t] = FLT_MAX; bi[t] = 0; }
    for (int tile = 0; tile < PPG; tile += 128) {
        int c = graph * PPG + tile + threadIdx.x;
        float cx = pos[3*c], cy = pos[3*c+1], cz = pos[3*c+2];
        cand[threadIdx.x] = make_float4(cx, cy, cz, cx*cx + cy*cy + cz*cz);
        __syncthreads();
#pragma unroll 4
        for (int u = 0; u < 128; u++) {
            float4 p = cand[u];
            int cidx = graph*PPG + tile + u;
            float d2a = as + p.w - 2.0f*(ax*p.x + ay*p.y + az*p.z);
            float d2b = bs + p.w - 2.0f*(bx*p.x + by*p.y + bz*p.z);
            if (d2a < ad[5]) {
                ad[5] = d2a; ai[5] = cidx;
#pragma unroll
                for (int t = 5; t > 0; t--)
                    if (ad[t] < ad[t-1]) {
                        float td = ad[t]; ad[t] = ad[t-1]; ad[t-1] = td;
                        int   ti = ai[t]; ai[t] = ai[t-1]; ai[t-1] = ti;
                    }
            }
            if (d2b < bd[5]) {
                bd[5] = d2b; bi[5] = cidx;
#pragma unroll
                for (int t = 5; t > 0; t--)
                    if (bd[t] < bd[t-1]) {
                        float td = bd[t]; bd[t] = bd[t-1]; bd[t-1] = td;
                        int   ti = bi[t]; bi[t] = bi[t-1]; bi[t-1] = ti;
                    }
            }
        }
        __syncthreads();
    }
#pragma unroll
    for (int t = 0; t < 6; t++) { g_knn[q0*8 + t] = ai[t]; g_knn[q1*8 + t] = bi[t]; }
    g_knn[q0*8 + 6] = ai[0]; g_knn[q0*8 + 7] = ai[0];
    g_knn[q1*8 + 6] = bi[0]; g_knn[q1*8 + 7] = bi[0];
}

// ---------------- merged weight split (W2 all layers + W1 layers 2/3) + zero g_pool ----------------
__global__ __launch_bounds__(128) void wsplit_kernel(const float* __restrict__ W2a,
                                                     const float* __restrict__ W2b,
                                                     const float* __restrict__ W2c,
                                                     const float* __restrict__ W1b,
                                                     const float* __restrict__ W1c)
{
    int t = blockIdx.x * 128 + threadIdx.x;        // 224 blocks: 12288 (W2) + 16384 (W1)
    if (t < BGRAPH * 64) g_pool[t] = 0u;           // re-zeroed every launch (graph-replay safe)
    if (t < 12288) {
        int l = t >> 12, nk = t & 4095;
        int n = nk >> 6, k = nk & 63;
        const float* W2 = (l == 0) ? W2a : ((l == 1) ? W2b : W2c);
        g_w2s[l][sw128((uint32_t)(n*128 + k*2)) >> 1] = __float2half_rn(W2[k*64 + n]);
    } else {
        int u = t - 12288;
        int l = u >> 13, nk = u & 8191;
        int n = nk >> 6, k = nk & 63;
        const float* W1 = l ? W1c : W1b;
        float v = (n < 64) ? W1[k*64 + n] : W1[(64 + k)*64 + (n - 64)];
        g_w1s[l][sw128((uint32_t)(n*128 + k*2)) >> 1] = __float2half_rn(v);
    }
}

// ---------------- phase B: W2 GEMM + max over slots + relu ----------------
// MODE 1 = FUSE (hC fp16, ALIASED onto W2 region -> sync after bh loads); MODE 2 = POOL (fp32 poolC)
template<int SLOTS, int MODE>
__device__ __forceinline__ void edge_phaseB(
    uint32_t sA, uint32_t sB,
    const float* __restrict__ b2, char* hC, float* poolC,
    int warp, int lane)
{
    const int rb = (warp >> 1) * 64;
    const int ch = (warp & 1) * 32;
    const int gn0 = (warp & 1) * 4;
    int acolb = (lane >> 4) * 16;

    uint32_t bh[4][4][2];
    {
        uint32_t laddr = (uint32_t)((lane & 7)*128 + ((lane >> 4) & 1)*32 + ((lane >> 3) & 1)*16);
#pragma unroll
        for (int nt = 0; nt < 4; nt++)
#pragma unroll
            for (int kp = 0; kp < 4; kp += 2) {
                uint32_t boff = sw128((uint32_t)((gn0 + nt)*1024 + kp*32) + laddr);
                uint32_t r[4];
                ldsm_x4(r, sB + boff);
                bh[nt][kp][0] = r[0]; bh[nt][kp][1] = r[1];
                bh[nt][kp+1][0] = r[2]; bh[nt][kp+1][1] = r[3];
            }
    }
    if (MODE == 1) __syncthreads();    // hC aliases W2 smem: all warps' bh must be in regs first

#pragma unroll
    for (int rt = 0; rt < 4; rt++) {
        uint32_t afr[4][4];
        uint32_t arow_off = (uint32_t)((rb + rt*16 + (lane & 15)) * 128);
#pragma unroll
        for (int k = 0; k < 4; k++)
            ldsm_x4(afr[k], sA + sw128(arow_off + k*32 + acolb));

#pragma unroll
        for (int nt = 0; nt < 4; nt++) {
            float d[4] = {0.f, 0.f, 0.f, 0.f};
#pragma unroll
            for (int k = 0; k < 4; k++) mma_16816(d, afr[k], bh[nt][k]);

            float m0 = d[0], m1 = d[1], m2 = d[2], m3 = d[3];
            if (SLOTS == 8) {
#pragma unroll
                for (int s = 4; s <= 16; s <<= 1) {
                    m0 = fmaxf(m0, __shfl_xor_sync(0xffffffffu, m0, s));
                    m1 = fmaxf(m1, __shfl_xor_sync(0xffffffffu, m1, s));
                    m2 = fmaxf(m2, __shfl_xor_sync(0xffffffffu, m2, s));
                    m3 = fmaxf(m3, __shfl_xor_sync(0xffffffffu, m3, s));
                }
                int col = ch + nt*8 + (lane & 3)*2;
                if (lane < 8) {
                    int lp = (warp >> 1) * 8 + rt * 2 + (lane >> 2);
                    float v0 = (lane < 4) ? m0 : m2;
                    float v1 = (lane < 4) ? m1 : m3;
                    v0 = fmaxf(v0 + b2[col], 0.f);
                    v1 = fmaxf(v1 + b2[col+1], 0.f);
                    *(uint32_t*)(hC + sw128((uint32_t)(lp*128 + col*2))) = pack_h2(v0, v1);
                }
            } else {   // SLOTS == 4
#pragma unroll
                for (int s = 4; s <= 8; s <<= 1) {
                    m0 = fmaxf(m0, __shfl_xor_sync(0xffffffffu, m0, s));
                    m1 = fmaxf(m1, __shfl_xor_sync(0xffffffffu, m1, s));
                    m2 = fmaxf(m2, __shfl_xor_sync(0xffffffffu, m2, s));
                    m3 = fmaxf(m3, __shfl_xor_sync(0xffffffffu, m3, s));
                }
                int col = ch + nt*8 + (lane & 3)*2;
                if ((lane & 15) < 4) {
                    int lpb = (warp >> 1) * 16 + rt * 4;
                    int g = lane >> 4;
                    float v0 = fmaxf(m0 + b2[col], 0.f), v1 = fmaxf(m1 + b2[col+1], 0.f);
                    float v2 = fmaxf(m2 + b2[col], 0.f), v3 = fmaxf(m3 + b2[col+1], 0.f);
                    if (MODE == 1) {
                        *(uint32_t*)(hC + sw128((uint32_t)((lpb + g)*128 + col*2)))     = pack_h2(v0, v1);
                        *(uint32_t*)(hC + sw128((uint32_t)((lpb + 2 + g)*128 + col*2))) = pack_h2(v2, v3);
                    } else {
                        *(float2*)&poolC[(lpb + g)*66 + col]     = make_float2(v0, v1);
                        *(float2*)&poolC[(lpb + 2 + g)*66 + col] = make_float2(v2, v3);
                    }
                }
            }
        }
    }
}

// ---------------- phase C: ab projection GEMM (h fp16 @ W1ab^T -> ab out FP16) ----------------
__device__ __forceinline__ void phaseC(
    uint32_t sH, uint32_t sW1, const float* __restrict__ b1n,
    __half* __restrict__ abot, int warp, int lane, int PTS, int pbase)
{
    int ntile = (PTS / 16) * 4;
    uint32_t laddr = (uint32_t)((lane & 7)*128 + ((lane >> 4) & 1)*32 + ((lane >> 3) & 1)*16);
    uint32_t acolb = (uint32_t)((lane >> 4) * 16);
    for (int t = warp; t < ntile; t += 8) {
        int rt = t >> 2, cg = t & 3;
        uint32_t afr[4][4];
        uint32_t arow = (uint32_t)((rt*16 + (lane & 15)) * 128);
#pragma unroll
        for (int k = 0; k < 4; k++)
            ldsm_x4(afr[k], sH + sw128(arow + k*32 + acolb));
#pragma unroll
        for (int nt = 0; nt < 4; nt++) {
            uint32_t bh[4][2];
#pragma unroll
            for (int kp = 0; kp < 4; kp += 2) {
                uint32_t bo = sw128((uint32_t)((cg*4 + nt)*1024 + kp*32) + laddr);
                uint32_t r[4];
                ldsm_x4(r, sW1 + bo);
                bh[kp][0] = r[0]; bh[kp][1] = r[1]; bh[kp+1][0] = r[2]; bh[kp+1][1] = r[3];
            }
            float d[4] = {0.f, 0.f, 0.f, 0.f};
#pragma unroll
            for (int k = 0; k < 4; k++) mma_16816(d, afr[k], bh[k]);
            int r0 = rt*16 + (lane >> 2);
            int col = cg*32 + nt*8 + (lane & 3)*2;
            float bx = 0.f, by = 0.f;
            if (col < 64) { bx = b1n[col]; by = b1n[col + 1]; }
            *(uint32_t*)&abot[(size_t)(pbase + r0)*128 + col]     = pack_h2(d[0] + bx, d[1] + by);
            *(uint32_t*)&abot[(size_t)(pbase + r0 + 8)*128 + col] = pack_h2(d[2] + bx, d[3] + by);
        }
    }
}

// smem layouts:
//   FUSE:  A 0..32K | W2->hC 32K..40K (aliased after bh load) | W1 40K..56K        -> 4 CTAs
//   POOL:  A 0..32K | W2 32K..40K | poolC 40K..40K+16896 (reduce scratch reuses A) -> 3 CTAs
#define EDGE_SMEM_F (32768 + 8192 + 16384 + 256)
#define EDGE_SMEM_P (32768 + 8192 + 64*66*4 + 256)

// ---------------- edge layer 1 (fused ab): inline pos projections; batched-MLP gathers ----------------
__global__ __launch_bounds__(256, 4) void edge1_mma_kernel(
    const float* __restrict__ W1,      // [9][64]
    const float* __restrict__ b1,
    const float* __restrict__ b2,
    const float* __restrict__ b1n,
    __half* __restrict__ abot)
{
    constexpr int PTS = 32;
    extern __shared__ char smem_raw[];
    uint32_t su = smem_u32(smem_raw);
    uint32_t abase = (su + 127) & ~127u;
    char* base = smem_raw + (abase - su);
    char* AC = base;
    char* hC = base + 32768;               // aliases W2 region after bh loads
    uint32_t sA = abase, sB = abase + 32768, sW1 = abase + 40960, sH = abase + 32768;

    int tid = threadIdx.x, warp = tid >> 5, lane = tid & 31;

    {
        const uint4* s2 = (const uint4*)g_w2s[0];
        uint4* d2p = (uint4*)(base + 32768);
        for (int t = tid; t < 512; t += 256) d2p[t] = s2[t];
        const uint4* s1 = (const uint4*)g_w1s[0];
        uint4* d1p = (uint4*)(base + 40960);
        for (int t = tid; t < 1024; t += 256) d1p[t] = s1[t];
    }

    {
        int lane2 = lane * 2;
        float wa0x=W1[lane2],       wa0y=W1[lane2+1];
        float wa1x=W1[64+lane2],    wa1y=W1[64+lane2+1];
        float wa2x=W1[128+lane2],   wa2y=W1[128+lane2+1];
        float wb0x=W1[192+lane2],   wb0y=W1[192+lane2+1];
        float wb1x=W1[256+lane2],   wb1y=W1[256+lane2+1];
        float wb2x=W1[320+lane2],   wb2y=W1[320+lane2+1];
        float wr0x=W1[384+lane2],   wr0y=W1[384+lane2+1];
        float wr1x=W1[448+lane2],   wr1y=W1[448+lane2+1];
        float wr2x=W1[512+lane2],   wr2y=W1[512+lane2+1];
        float b1x=b1[lane2], b1y=b1[lane2+1];
#pragma unroll
        for (int pp = 0; pp < 4; pp++) {
            int lp = warp * 4 + pp;
            int i = blockIdx.x * PTS + lp;
            // batched index + position loads (all independent -> high MLP)
            int4 kra = *(const int4*)&g_knn[i*8];
            int2 krb = *(const int2*)&g_knn[i*8 + 4];
            int js[6] = {kra.x, kra.y, kra.z, kra.w, krb.x, krb.y};
            float4 pi = g_pos4[i];
            float4 pj[6];
#pragma unroll
            for (int s = 0; s < 6; s++) pj[s] = g_pos4[js[s]];
            float ax = fmaf(pi.x, wa0x, fmaf(pi.y, wa1x, fmaf(pi.z, wa2x, b1x)));
            float ay = fmaf(pi.x, wa0y, fmaf(pi.y, wa1y, fmaf(pi.z, wa2y, b1y)));
            int rowbase = lp * 8;
#pragma unroll
            for (int slot = 0; slot < 6; slot++) {
                float rx = pj[slot].x - pi.x, ry = pj[slot].y - pi.y, rz = pj[slot].z - pi.z;
                float h0 = ax;
                h0 = fmaf(pj[slot].x, wb0x, h0); h0 = fmaf(pj[slot].y, wb1x, h0); h0 = fmaf(pj[slot].z, wb2x, h0);
                h0 = fmaf(rx, wr0x, h0);   h0 = fmaf(ry, wr1x, h0);   h0 = fmaf(rz, wr2x, h0);
                float h1 = ay;
                h1 = fmaf(pj[slot].x, wb0y, h1); h1 = fmaf(pj[slot].y, wb1y, h1); h1 = fmaf(pj[slot].z, wb2y, h1);
                h1 = fmaf(rx, wr0y, h1);   h1 = fmaf(ry, wr1y, h1);   h1 = fmaf(rz, wr2y, h1);
                h0 = fmaxf(h0, 0.f); h1 = fmaxf(h1, 0.f);
                uint32_t pk = pack_h2(h0, h1);
                *(uint32_t*)(AC + sw128((uint32_t)((rowbase + slot)*128 + lane2*2))) = pk;
                if (slot == 0) {
                    *(uint32_t*)(AC + sw128((uint32_t)((rowbase + 6)*128 + lane2*2))) = pk;
                    *(uint32_t*)(AC + sw128((uint32_t)((rowbase + 7)*128 + lane2*2))) = pk;
                }
            }
        }
    }
    __syncthreads();
    edge_phaseB<8, 1>(sA, sB, b2, hC, nullptr, warp, lane);
    __syncthreads();
    phaseC(sH, sW1, b1n, abot, warp, lane, PTS, blockIdx.x * PTS);
}

// ---------------- edge layers 2/3: batched-MLP gathers; MODE 1=fused ab out, 2=pool ----------------
template<int K, int SLOTS, int MODE>
__global__ __launch_bounds__(256, (MODE == 2 ? 3 : 4)) void edge_mma_kernel(
    const __half* __restrict__ abin,
    const float* __restrict__ W1rel,
    const float* __restrict__ b2,
    int layer,
    int w1layer,
    const float* __restrict__ b1n,
    __half* __restrict__ abot)
{
    constexpr int PTS = 256 / SLOTS;
    constexpr int PPW = PTS / 8;
    extern __shared__ char smem_raw[];
    uint32_t su = smem_u32(smem_raw);
    uint32_t abase = (su + 127) & ~127u;
    char* base = smem_raw + (abase - su);
    char* AC = base;
    char* hC = base + 32768;                 // MODE 1: aliases W2 region
    float* poolC = (float*)(base + 40960);   // MODE 2
    uint32_t sA = abase, sB = abase + 32768, sW1 = abase + 40960, sH = abase + 32768;

    int tid = threadIdx.x, warp = tid >> 5, lane = tid & 31;

    {
        const uint4* s2 = (const uint4*)g_w2s[layer];
        uint4* d2p = (uint4*)(base + 32768);
        for (int t = tid; t < 512; t += 256) d2p[t] = s2[t];
        if (MODE == 1) {
            const uint4* s1 = (const uint4*)g_w1s[w1layer];
            uint4* d1p = (uint4*)(base + 40960);
            for (int t = tid; t < 1024; t += 256) d1p[t] = s1[t];
        }
    }

    {
        int lane2 = lane * 2;
        float u0x = W1rel[lane2],       u0y = W1rel[lane2 + 1];
        float u1x = W1rel[64 + lane2],  u1y = W1rel[64 + lane2 + 1];
        float u2x = W1rel[128 + lane2], u2y = W1rel[128 + lane2 + 1];
#pragma unroll
        for (int pp = 0; pp < PPW; pp++) {
            int lp = warp * PPW + pp;
            int i = blockIdx.x * PTS + lp;
            // batched loads: knn row as int4, then all K pj/b in flight together
            int4 kr = *(const int4*)&g_knn[i*8];
            int js[4] = {kr.x, kr.y, kr.z, (K > 3) ? kr.w : kr.x};
            float4 pi = g_pos4[i];
            float2 a = __half22float2(*(const __half2*)&abin[(size_t)i*128 + lane2]);
            float4 pj[K]; float2 b[K];
#pragma unroll
            for (int s = 0; s < K; s++) {
                pj[s] = g_pos4[js[s]];
                b[s]  = __half22float2(*(const __half2*)&abin[(size_t)js[s]*128 + 64 + lane2]);
            }
            int rowbase = lp * SLOTS;
#pragma unroll
            for (int slot = 0; slot < K; slot++) {
                float rx = pj[slot].x - pi.x, ry = pj[slot].y - pi.y, rz = pj[slot].z - pi.z;
                float h0 = fmaxf(fmaf(rx, u0x, fmaf(ry, u1x, fmaf(rz, u2x, a.x + b[slot].x))), 0.f);
                float h1 = fmaxf(fmaf(rx, u0y, fmaf(ry, u1y, fmaf(rz, u2y, a.y + b[slot].y))), 0.f);
                uint32_t pk = pack_h2(h0, h1);
                *(uint32_t*)(AC + sw128((uint32_t)((rowbase + slot)*128 + lane2*2))) = pk;
                if (slot == 0) {
#pragma unroll
                    for (int e = K; e < SLOTS; e++)
                        *(uint32_t*)(AC + sw128((uint32_t)((rowbase + e)*128 + lane2*2))) = pk;
                }
            }
        }
    }
    __syncthreads();
    edge_phaseB<SLOTS, MODE>(sA, sB, b2, hC, poolC, warp, lane);
    if (MODE == 1) {
        __syncthreads();
        phaseC(sH, sW1, b1n, abot, warp, lane, PTS, blockIdx.x * PTS);
    }
    if (MODE == 2) {
        __syncthreads();
        float* red = (float*)AC;
        int col = tid & 63, grp = tid >> 6;
        float m = 0.f;
        for (int r = grp; r < 64; r += 4) m = fmaxf(m, poolC[r*66 + col]);
        red[grp*64 + col] = m;
        __syncthreads();
        if (grp == 0) {
            m = fmaxf(fmaxf(red[col], red[64 + col]), fmaxf(red[128 + col], red[192 + col]));
            int graph = blockIdx.x >> 4;
            atomicMax(&g_pool[graph*64 + col], __float_as_uint(m));
        }
    }
}

// ---------------- regression head: out = pool @ regW + regb ----------------
__global__ __launch_bounds__(64) void head_kernel(const float* __restrict__ regW,
                                                  const float* __restrict__ regb,
                                                  float* __restrict__ out)
{
    __shared__ float hv[64];
    int g = blockIdx.x, tid = threadIdx.x;
    hv[tid] = __uint_as_float(g_pool[g*64 + tid]);
    __syncthreads();
    if (tid < 6) {
        float acc = regb[tid];
#pragma unroll
        for (int c = 0; c < 64; c++)
            acc = fmaf(hv[c], regW[c*6 + tid], acc);
        out[g*6 + tid] = acc;
    }
}

// ---------------- launch ----------------
extern "C" void kernel_launch(void* const* d_in, const int* in_sizes, int n_in,
                              void* d_out, int out_size)
{
    (void)in_sizes; (void)n_in; (void)out_size;
    const float* pos  = (const float*)d_in[1];
    const float* c1W1 = (const float*)d_in[3];
    const float* c1b1 = (const float*)d_in[4];
    const float* c1W2 = (const float*)d_in[5];
    const float* c1b2 = (const float*)d_in[6];
    const float* c2W1 = (const float*)d_in[7];
    const float* c2b1 = (const float*)d_in[8];
    const float* c2W2 = (const float*)d_in[9];
    const float* c2b2 = (const float*)d_in[10];
    const float* c3W1 = (const float*)d_in[11];
    const float* c3b1 = (const float*)d_in[12];
    const float* c3W2 = (const float*)d_in[13];
    const float* c3b2 = (const float*)d_in[14];
    const float* regW = (const float*)d_in[15];
    const float* regb = (const float*)d_in[16];
    float* out = (float*)d_out;

    __half *abA, *abB;
    cudaGetSymbolAddress((void**)&abA, g_abA);
    cudaGetSymbolAddress((void**)&abB, g_abB);
    cudaFuncSetAttribute((const void*)edge1_mma_kernel, cudaFuncAttributeMaxDynamicSharedMemorySize, EDGE_SMEM_F);
    cudaFuncSetAttribute((const void*)edge_mma_kernel<4,4,1>, cudaFuncAttributeMaxDynamicSharedMemorySize, EDGE_SMEM_F);
    cudaFuncSetAttribute((const void*)edge_mma_kernel<3,4,2>, cudaFuncAttributeMaxDynamicSharedMemorySize, EDGE_SMEM_P);

    knn_kernel<<<BGRAPH * 4, 128>>>(pos);
    wsplit_kernel<<<224, 128>>>(c1W2, c2W2, c3W2, c2W1, c3W1);   // also zeroes g_pool
    edge1_mma_kernel<<<NPTS/32, 256, EDGE_SMEM_F>>>(c1W1, c1b1, c1b2, c2b1, abA);
    edge_mma_kernel<4,4,1><<<NPTS/64, 256, EDGE_SMEM_F>>>(abA, c2W1 + 128*64, c2b2, 1, 1, c3b1, abB);
    edge_mma_kernel<3,4,2><<<NPTS/64, 256, EDGE_SMEM_P>>>(abB, c3W1 + 128*64, c3b2, 2, 0, nullptr, nullptr);
    head_kernel<<<BGRAPH, 64>>>(regW, regb, out);
}

// round 17
// speedup vs baseline: 1.0333x; 1.0333x over previous
#include <cuda_runtime.h>
#include <cuda_fp16.h>
#include <float.h>
#include <stdint.h>

#define NPTS   65536
#define BGRAPH 64
#define PPG    1024

// ---------------- scratch (device globals; no allocation) ----------------
__device__ int      g_knn[NPTS * 8];          // 6 real + 2 pad (dup of nn0)
__device__ __half   g_abA[NPTS * 128];        // fp16: a (+b1) cols 0..63, b cols 64..127
__device__ __half   g_abB[NPTS * 128];        // fp16 double buffer (layer-3 input)
__device__ float4   g_pos4[NPTS];             // packed positions (x,y,z,0)
__device__ uint32_t g_pool[BGRAPH * 64];      // per-graph channel max (uint-ordered floats >= 0)
__device__ __align__(16) __half g_w2s[3][4096];  // [layer] swizzled fp16 W2^T [n=64][k=64]
__device__ __align__(16) __half g_w1s[2][8192];  // [layer] swizzled fp16 W1ab^T [n=128][k=64]

// ---------------- helpers (base-ISA: ldmatrix + mma.sync, sm_80+) ----------------
__device__ __forceinline__ uint32_t smem_u32(const void* p) {
    uint32_t a;
    asm("{ .reg .u64 t; cvta.to.shared.u64 t, %1; cvt.u32.u64 %0, t; }" : "=r"(a) : "l"(p));
    return a;
}
__device__ __forceinline__ uint32_t sw128(uint32_t off) { return off ^ ((off >> 3) & 0x70); }
__device__ __forceinline__ uint32_t pack_h2(float a, float b) {
    __half2 h = __floats2half2_rn(a, b);
    return *reinterpret_cast<uint32_t*>(&h);
}
__device__ __forceinline__ void ldsm_x4(uint32_t* r, uint32_t addr) {
    asm volatile("ldmatrix.sync.aligned.m8n8.x4.shared.b16 {%0,%1,%2,%3}, [%4];"
                 : "=r"(r[0]), "=r"(r[1]), "=r"(r[2]), "=r"(r[3]) : "r"(addr));
}
__device__ __forceinline__ void mma_16816(float* d, const uint32_t* a, const uint32_t* b) {
    asm volatile("mma.sync.aligned.m16n8k16.row.col.f32.f16.f16.f32 "
                 "{%0,%1,%2,%3}, {%4,%5,%6,%7}, {%8,%9}, {%0,%1,%2,%3};"
                 : "+f"(d[0]), "+f"(d[1]), "+f"(d[2]), "+f"(d[3])
                 : "r"(a[0]), "r"(a[1]), "r"(a[2]), "r"(a[3]), "r"(b[0]), "r"(b[1]));
}

// ---------------- kNN (k=6, 2 queries/thread, 4 blocks/graph; matches jax top_k ties) ----------------
__global__ __launch_bounds__(128) void knn_kernel(const float* __restrict__ pos)
{
    __shared__ float4 cand[128];
    int graph = blockIdx.x >> 2;
    int q0 = graph * PPG + ((blockIdx.x & 3) << 8) + threadIdx.x;
    int q1 = q0 + 128;
    float ax = pos[3*q0], ay = pos[3*q0+1], az = pos[3*q0+2];
    float bx = pos[3*q1], by = pos[3*q1+1], bz = pos[3*q1+2];
    float as = ax*ax + ay*ay + az*az;
    float bs = bx*bx + by*by + bz*bz;
    g_pos4[q0] = make_float4(ax, ay, az, 0.f);
    g_pos4[q1] = make_float4(bx, by, bz, 0.f);
    float ad[6], bd[6]; int ai[6], bi[6];
#pragma unroll
    for (int t = 0; t < 6; t++) { ad[t] = FLT_MAX; ai[t] = 0; bd[t] = FLT_MAX; bi[t] = 0; }
    for (int tile = 0; tile < PPG; tile += 128) {
        int c = graph * PPG + tile + threadIdx.x;
        float cx = pos[3*c], cy = pos[3*c+1], cz = pos[3*c+2];
        cand[threadIdx.x] = make_float4(cx, cy, cz, cx*cx + cy*cy + cz*cz);
        __syncthreads();
#pragma unroll 4
        for (int u = 0; u < 128; u++) {
            float4 p = cand[u];
            int cidx = graph*PPG + tile + u;
            float d2a = as + p.w - 2.0f*(ax*p.x + ay*p.y + az*p.z);
            float d2b = bs + p.w - 2.0f*(bx*p.x + by*p.y + bz*p.z);
            if (d2a < ad[5]) {
                ad[5] = d2a; ai[5] = cidx;
#pragma unroll
                for (int t = 5; t > 0; t--)
                    if (ad[t] < ad[t-1]) {
                        float td = ad[t]; ad[t] = ad[t-1]; ad[t-1] = td;
                        int   ti = ai[t]; ai[t] = ai[t-1]; ai[t-1] = ti;
                    }
            }
            if (d2b < bd[5]) {
                bd[5] = d2b; bi[5] = cidx;
#pragma unroll
                for (int t = 5; t > 0; t--)
                    if (bd[t] < bd[t-1]) {
                        float td = bd[t]; bd[t] = bd[t-1]; bd[t-1] = td;
                        int   ti = bi[t]; bi[t] = bi[t-1]; bi[t-1] = ti;
                    }
            }
        }
        __syncthreads();
    }
#pragma unroll
    for (int t = 0; t < 6; t++) { g_knn[q0*8 + t] = ai[t]; g_knn[q1*8 + t] = bi[t]; }
    g_knn[q0*8 + 6] = ai[0]; g_knn[q0*8 + 7] = ai[0];
    g_knn[q1*8 + 6] = bi[0]; g_knn[q1*8 + 7] = bi[0];
}

// ---------------- merged weight split (W2 all layers + W1 layers 2/3) + zero g_pool ----------------
__global__ __launch_bounds__(128) void wsplit_kernel(const float* __restrict__ W2a,
                                                     const float* __restrict__ W2b,
                                                     const float* __restrict__ W2c,
                                                     const float* __restrict__ W1b,
                                                     const float* __restrict__ W1c)
{
    int t = blockIdx.x * 128 + threadIdx.x;        // 224 blocks: 12288 (W2) + 16384 (W1)
    if (t < BGRAPH * 64) g_pool[t] = 0u;           // re-zeroed every launch (graph-replay safe)
    if (t < 12288) {
        int l = t >> 12, nk = t & 4095;
        int n = nk >> 6, k = nk & 63;
        const float* W2 = (l == 0) ? W2a : ((l == 1) ? W2b : W2c);
        g_w2s[l][sw128((uint32_t)(n*128 + k*2)) >> 1] = __float2half_rn(W2[k*64 + n]);
    } else {
        int u = t - 12288;
        int l = u >> 13, nk = u & 8191;
        int n = nk >> 6, k = nk & 63;
        const float* W1 = l ? W1c : W1b;
        float v = (n < 64) ? W1[k*64 + n] : W1[(64 + k)*64 + (n - 64)];
        g_w1s[l][sw128((uint32_t)(n*128 + k*2)) >> 1] = __float2half_rn(v);
    }
}

// ---------------- phase B: W2 GEMM + max over slots + relu ----------------
// MODE 1 = FUSE (hC fp16, ALIASED onto W2 region -> sync after bh loads); MODE 2 = POOL (fp32 poolC)
template<int SLOTS, int MODE>
__device__ __forceinline__ void edge_phaseB(
    uint32_t sA, uint32_t sB,
    const float* __restrict__ b2, char* hC, float* poolC,
    int warp, int lane)
{
    const int rb = (warp >> 1) * 64;
    const int ch = (warp & 1) * 32;
    const int gn0 = (warp & 1) * 4;
    int acolb = (lane >> 4) * 16;

    uint32_t bh[4][4][2];
    {
        uint32_t laddr = (uint32_t)((lane & 7)*128 + ((lane >> 4) & 1)*32 + ((lane >> 3) & 1)*16);
#pragma unroll
        for (int nt = 0; nt < 4; nt++)
#pragma unroll
            for (int kp = 0; kp < 4; kp += 2) {
                uint32_t boff = sw128((uint32_t)((gn0 + nt)*1024 + kp*32) + laddr);
                uint32_t r[4];
                ldsm_x4(r, sB + boff);
                bh[nt][kp][0] = r[0]; bh[nt][kp][1] = r[1];
                bh[nt][kp+1][0] = r[2]; bh[nt][kp+1][1] = r[3];
            }
    }
    if (MODE == 1) __syncthreads();    // hC aliases W2 smem: all warps' bh must be in regs first

#pragma unroll
    for (int rt = 0; rt < 4; rt++) {
        uint32_t afr[4][4];
        uint32_t arow_off = (uint32_t)((rb + rt*16 + (lane & 15)) * 128);
#pragma unroll
        for (int k = 0; k < 4; k++)
            ldsm_x4(afr[k], sA + sw128(arow_off + k*32 + acolb));

#pragma unroll
        for (int nt = 0; nt < 4; nt++) {
            float d[4] = {0.f, 0.f, 0.f, 0.f};
#pragma unroll
            for (int k = 0; k < 4; k++) mma_16816(d, afr[k], bh[nt][k]);

            float m0 = d[0], m1 = d[1], m2 = d[2], m3 = d[3];
            if (SLOTS == 8) {
#pragma unroll
                for (int s = 4; s <= 16; s <<= 1) {
                    m0 = fmaxf(m0, __shfl_xor_sync(0xffffffffu, m0, s));
                    m1 = fmaxf(m1, __shfl_xor_sync(0xffffffffu, m1, s));
                    m2 = fmaxf(m2, __shfl_xor_sync(0xffffffffu, m2, s));
                    m3 = fmaxf(m3, __shfl_xor_sync(0xffffffffu, m3, s));
                }
                int col = ch + nt*8 + (lane & 3)*2;
                if (lane < 8) {
                    int lp = (warp >> 1) * 8 + rt * 2 + (lane >> 2);
                    float v0 = (lane < 4) ? m0 : m2;
                    float v1 = (lane < 4) ? m1 : m3;
                    v0 = fmaxf(v0 + b2[col], 0.f);
                    v1 = fmaxf(v1 + b2[col+1], 0.f);
                    *(uint32_t*)(hC + sw128((uint32_t)(lp*128 + col*2))) = pack_h2(v0, v1);
                }
            } else {   // SLOTS == 4
#pragma unroll
                for (int s = 4; s <= 8; s <<= 1) {
                    m0 = fmaxf(m0, __shfl_xor_sync(0xffffffffu, m0, s));
                    m1 = fmaxf(m1, __shfl_xor_sync(0xffffffffu, m1, s));
                    m2 = fmaxf(m2, __shfl_xor_sync(0xffffffffu, m2, s));
                    m3 = fmaxf(m3, __shfl_xor_sync(0xffffffffu, m3, s));
                }
                int col = ch + nt*8 + (lane & 3)*2;
                if ((lane & 15) < 4) {
                    int lpb = (warp >> 1) * 16 + rt * 4;
                    int g = lane >> 4;
                    float v0 = fmaxf(m0 + b2[col], 0.f), v1 = fmaxf(m1 + b2[col+1], 0.f);
                    float v2 = fmaxf(m2 + b2[col], 0.f), v3 = fmaxf(m3 + b2[col+1], 0.f);
                    if (MODE == 1) {
                        *(uint32_t*)(hC + sw128((uint32_t)((lpb + g)*128 + col*2)))     = pack_h2(v0, v1);
                        *(uint32_t*)(hC + sw128((uint32_t)((lpb + 2 + g)*128 + col*2))) = pack_h2(v2, v3);
                    } else {
                        *(float2*)&poolC[(lpb + g)*66 + col]     = make_float2(v0, v1);
                        *(float2*)&poolC[(lpb + 2 + g)*66 + col] = make_float2(v2, v3);
                    }
                }
            }
        }
    }
}

// ---------------- phase C: ab projection GEMM (h fp16 @ W1ab^T -> ab out FP16) ----------------
__device__ __forceinline__ void phaseC(
    uint32_t sH, uint32_t sW1, const float* __restrict__ b1n,
    __half* __restrict__ abot, int warp, int lane, int PTS, int pbase)
{
    int ntile = (PTS / 16) * 4;
    uint32_t laddr = (uint32_t)((lane & 7)*128 + ((lane >> 4) & 1)*32 + ((lane >> 3) & 1)*16);
    uint32_t acolb = (uint32_t)((lane >> 4) * 16);
    for (int t = warp; t < ntile; t += 8) {
        int rt = t >> 2, cg = t & 3;
        uint32_t afr[4][4];
        uint32_t arow = (uint32_t)((rt*16 + (lane & 15)) * 128);
#pragma unroll
        for (int k = 0; k < 4; k++)
            ldsm_x4(afr[k], sH + sw128(arow + k*32 + acolb));
#pragma unroll
        for (int nt = 0; nt < 4; nt++) {
            uint32_t bh[4][2];
#pragma unroll
            for (int kp = 0; kp < 4; kp += 2) {
                uint32_t bo = sw128((uint32_t)((cg*4 + nt)*1024 + kp*32) + laddr);
                uint32_t r[4];
                ldsm_x4(r, sW1 + bo);
                bh[kp][0] = r[0]; bh[kp][1] = r[1]; bh[kp+1][0] = r[2]; bh[kp+1][1] = r[3];
            }
            float d[4] = {0.f, 0.f, 0.f, 0.f};
#pragma unroll
            for (int k = 0; k < 4; k++) mma_16816(d, afr[k], bh[k]);
            int r0 = rt*16 + (lane >> 2);
            int col = cg*32 + nt*8 + (lane & 3)*2;
            float bx = 0.f, by = 0.f;
            if (col < 64) { bx = b1n[col]; by = b1n[col + 1]; }
            *(uint32_t*)&abot[(size_t)(pbase + r0)*128 + col]     = pack_h2(d[0] + bx, d[1] + by);
            *(uint32_t*)&abot[(size_t)(pbase + r0 + 8)*128 + col] = pack_h2(d[2] + bx, d[3] + by);
        }
    }
}

// smem layouts:
//   FUSE:  A 0..32K | W2->hC 32K..40K (aliased after bh load) | W1 40K..56K        -> 3 CTAs (regs freed)
//   POOL:  A 0..32K | W2 32K..40K | poolC 40K..40K+16896 (reduce scratch reuses A) -> 3 CTAs
#define EDGE_SMEM_F (32768 + 8192 + 16384 + 256)
#define EDGE_SMEM_P (32768 + 8192 + 64*66*4 + 256)

// ---------------- edge layer 1 (fused ab): inline pos projections; batched-MLP gathers ----------------
__global__ __launch_bounds__(256, 3) void edge1_mma_kernel(
    const float* __restrict__ W1,      // [9][64]
    const float* __restrict__ b1,
    const float* __restrict__ b2,
    const float* __restrict__ b1n,
    __half* __restrict__ abot)
{
    constexpr int PTS = 32;
    extern __shared__ char smem_raw[];
    uint32_t su = smem_u32(smem_raw);
    uint32_t abase = (su + 127) & ~127u;
    char* base = smem_raw + (abase - su);
    char* AC = base;
    char* hC = base + 32768;               // aliases W2 region after bh loads
    uint32_t sA = abase, sB = abase + 32768, sW1 = abase + 40960, sH = abase + 32768;

    int tid = threadIdx.x, warp = tid >> 5, lane = tid & 31;

    {
        const uint4* s2 = (const uint4*)g_w2s[0];
        uint4* d2p = (uint4*)(base + 32768);
        for (int t = tid; t < 512; t += 256) d2p[t] = s2[t];
        const uint4* s1 = (const uint4*)g_w1s[0];
        uint4* d1p = (uint4*)(base + 40960);
        for (int t = tid; t < 1024; t += 256) d1p[t] = s1[t];
    }

    {
        int lane2 = lane * 2;
        float wa0x=W1[lane2],       wa0y=W1[lane2+1];
        float wa1x=W1[64+lane2],    wa1y=W1[64+lane2+1];
        float wa2x=W1[128+lane2],   wa2y=W1[128+lane2+1];
        float wb0x=W1[192+lane2],   wb0y=W1[192+lane2+1];
        float wb1x=W1[256+lane2],   wb1y=W1[256+lane2+1];
        float wb2x=W1[320+lane2],   wb2y=W1[320+lane2+1];
        float wr0x=W1[384+lane2],   wr0y=W1[384+lane2+1];
        float wr1x=W1[448+lane2],   wr1y=W1[448+lane2+1];
        float wr2x=W1[512+lane2],   wr2y=W1[512+lane2+1];
        float b1x=b1[lane2], b1y=b1[lane2+1];
#pragma unroll
        for (int pp = 0; pp < 4; pp++) {
            int lp = warp * 4 + pp;
            int i = blockIdx.x * PTS + lp;
            int4 kra = *(const int4*)&g_knn[i*8];
            int2 krb = *(const int2*)&g_knn[i*8 + 4];
            int js[6] = {kra.x, kra.y, kra.z, kra.w, krb.x, krb.y};
            float4 pi = g_pos4[i];
            float4 pj[6];
#pragma unroll
            for (int s = 0; s < 6; s++) pj[s] = g_pos4[js[s]];
            float ax = fmaf(pi.x, wa0x, fmaf(pi.y, wa1x, fmaf(pi.z, wa2x, b1x)));
            float ay = fmaf(pi.x, wa0y, fmaf(pi.y, wa1y, fmaf(pi.z, wa2y, b1y)));
            int rowbase = lp * 8;
#pragma unroll
            for (int slot = 0; slot < 6; slot++) {
                float rx = pj[slot].x - pi.x, ry = pj[slot].y - pi.y, rz = pj[slot].z - pi.z;
                float h0 = ax;
                h0 = fmaf(pj[slot].x, wb0x, h0); h0 = fmaf(pj[slot].y, wb1x, h0); h0 = fmaf(pj[slot].z, wb2x, h0);
                h0 = fmaf(rx, wr0x, h0);   h0 = fmaf(ry, wr1x, h0);   h0 = fmaf(rz, wr2x, h0);
                float h1 = ay;
                h1 = fmaf(pj[slot].x, wb0y, h1); h1 = fmaf(pj[slot].y, wb1y, h1); h1 = fmaf(pj[slot].z, wb2y, h1);
                h1 = fmaf(rx, wr0y, h1);   h1 = fmaf(ry, wr1y, h1);   h1 = fmaf(rz, wr2y, h1);
                h0 = fmaxf(h0, 0.f); h1 = fmaxf(h1, 0.f);
                uint32_t pk = pack_h2(h0, h1);
                *(uint32_t*)(AC + sw128((uint32_t)((rowbase + slot)*128 + lane2*2))) = pk;
                if (slot == 0) {
                    *(uint32_t*)(AC + sw128((uint32_t)((rowbase + 6)*128 + lane2*2))) = pk;
                    *(uint32_t*)(AC + sw128((uint32_t)((rowbase + 7)*128 + lane2*2))) = pk;
                }
            }
        }
    }
    __syncthreads();
    edge_phaseB<8, 1>(sA, sB, b2, hC, nullptr, warp, lane);
    __syncthreads();
    phaseC(sH, sW1, b1n, abot, warp, lane, PTS, blockIdx.x * PTS);
}

// ---------------- edge layers 2/3: batched-MLP gathers; MODE 1=fused ab out, 2=pool ----------------
template<int K, int SLOTS, int MODE>
__global__ __launch_bounds__(256, 3) void edge_mma_kernel(
    const __half* __restrict__ abin,
    const float* __restrict__ W1rel,
    const float* __restrict__ b2,
    int layer,
    int w1layer,
    const float* __restrict__ b1n,
    __half* __restrict__ abot)
{
    constexpr int PTS = 256 / SLOTS;
    constexpr int PPW = PTS / 8;
    extern __shared__ char smem_raw[];
    uint32_t su = smem_u32(smem_raw);
    uint32_t abase = (su + 127) & ~127u;
    char* base = smem_raw + (abase - su);
    char* AC = base;
    char* hC = base + 32768;                 // MODE 1: aliases W2 region
    float* poolC = (float*)(base + 40960);   // MODE 2
    uint32_t sA = abase, sB = abase + 32768, sW1 = abase + 40960, sH = abase + 32768;

    int tid = threadIdx.x, warp = tid >> 5, lane = tid & 31;

    {
        const uint4* s2 = (const uint4*)g_w2s[layer];
        uint4* d2p = (uint4*)(base + 32768);
        for (int t = tid; t < 512; t += 256) d2p[t] = s2[t];
        if (MODE == 1) {
            const uint4* s1 = (const uint4*)g_w1s[w1layer];
            uint4* d1p = (uint4*)(base + 40960);
            for (int t = tid; t < 1024; t += 256) d1p[t] = s1[t];
        }
    }

    {
        int lane2 = lane * 2;
        float u0x = W1rel[lane2],       u0y = W1rel[lane2 + 1];
        float u1x = W1rel[64 + lane2],  u1y = W1rel[64 + lane2 + 1];
        float u2x = W1rel[128 + lane2], u2y = W1rel[128 + lane2 + 1];
#pragma unroll
        for (int pp = 0; pp < PPW; pp++) {
            int lp = warp * PPW + pp;
            int i = blockIdx.x * PTS + lp;
            int4 kr = *(const int4*)&g_knn[i*8];
            int js[4] = {kr.x, kr.y, kr.z, (K > 3) ? kr.w : kr.x};
            float4 pi = g_pos4[i];
            float2 a = __half22float2(*(const __half2*)&abin[(size_t)i*128 + lane2]);
            float4 pj[K]; float2 b[K];
#pragma unroll
            for (int s = 0; s < K; s++) {
                pj[s] = g_pos4[js[s]];
                b[s]  = __half22float2(*(const __half2*)&abin[(size_t)js[s]*128 + 64 + lane2]);
            }
            int rowbase = lp * SLOTS;
#pragma unroll
            for (int slot = 0; slot < K; slot++) {
                float rx = pj[slot].x - pi.x, ry = pj[slot].y - pi.y, rz = pj[slot].z - pi.z;
                float h0 = fmaxf(fmaf(rx, u0x, fmaf(ry, u1x, fmaf(rz, u2x, a.x + b[slot].x))), 0.f);
                float h1 = fmaxf(fmaf(rx, u0y, fmaf(ry, u1y, fmaf(rz, u2y, a.y + b[slot].y))), 0.f);
                uint32_t pk = pack_h2(h0, h1);
                *(uint32_t*)(AC + sw128((uint32_t)((rowbase + slot)*128 + lane2*2))) = pk;
                if (slot == 0) {
#pragma unroll
                    for (int e = K; e < SLOTS; e++)
                        *(uint32_t*)(AC + sw128((uint32_t)((rowbase + e)*128 + lane2*2))) = pk;
                }
            }
        }
    }
    __syncthreads();
    edge_phaseB<SLOTS, MODE>(sA, sB, b2, hC, poolC, warp, lane);
    if (MODE == 1) {
        __syncthreads();
        phaseC(sH, sW1, b1n, abot, warp, lane, PTS, blockIdx.x * PTS);
    }
    if (MODE == 2) {
        __syncthreads();
        float* red = (float*)AC;
        int col = tid & 63, grp = tid >> 6;
        float m = 0.f;
        for (int r = grp; r < 64; r += 4) m = fmaxf(m, poolC[r*66 + col]);
        red[grp*64 + col] = m;
        __syncthreads();
        if (grp == 0) {
            m = fmaxf(fmaxf(red[col], red[64 + col]), fmaxf(red[128 + col], red[192 + col]));
            int graph = blockIdx.x >> 4;
            atomicMax(&g_pool[graph*64 + col], __float_as_uint(m));
        }
    }
}

// ---------------- regression head: out = pool @ regW + regb ----------------
__global__ __launch_bounds__(64) void head_kernel(const float* __restrict__ regW,
                                                  const float* __restrict__ regb,
                                                  float* __restrict__ out)
{
    __shared__ float hv[64];
    int g = blockIdx.x, tid = threadIdx.x;
    hv[tid] = __uint_as_float(g_pool[g*64 + tid]);
    __syncthreads();
    if (tid < 6) {
        float acc = regb[tid];
#pragma unroll
        for (int c = 0; c < 64; c++)
            acc = fmaf(hv[c], regW[c*6 + tid], acc);
        out[g*6 + tid] = acc;
    }
}

// ---------------- launch ----------------
extern "C" void kernel_launch(void* const* d_in, const int* in_sizes, int n_in,
                              void* d_out, int out_size)
{
    (void)in_sizes; (void)n_in; (void)out_size;
    const float* pos  = (const float*)d_in[1];
    const float* c1W1 = (const float*)d_in[3];
    const float* c1b1 = (const float*)d_in[4];
    const float* c1W2 = (const float*)d_in[5];
    const float* c1b2 = (const float*)d_in[6];
    const float* c2W1 = (const float*)d_in[7];
    const float* c2b1 = (const float*)d_in[8];
    const float* c2W2 = (const float*)d_in[9];
    const float* c2b2 = (const float*)d_in[10];
    const float* c3W1 = (const float*)d_in[11];
    const float* c3b1 = (const float*)d_in[12];
    const float* c3W2 = (const float*)d_in[13];
    const float* c3b2 = (const float*)d_in[14];
    const float* regW = (const float*)d_in[15];
    const float* regb = (const float*)d_in[16];
    float* out = (float*)d_out;

    __half *abA, *abB;
    cudaGetSymbolAddress((void**)&abA, g_abA);
    cudaGetSymbolAddress((void**)&abB, g_abB);
    cudaFuncSetAttribute((const void*)edge1_mma_kernel, cudaFuncAttributeMaxDynamicSharedMemorySize, EDGE_SMEM_F);
    cudaFuncSetAttribute((const void*)edge_mma_kernel<4,4,1>, cudaFuncAttributeMaxDynamicSharedMemorySize, EDGE_SMEM_F);
    cudaFuncSetAttribute((const void*)edge_mma_kernel<3,4,2>, cudaFuncAttributeMaxDynamicSharedMemorySize, EDGE_SMEM_P);

    knn_kernel<<<BGRAPH * 4, 128>>>(pos);
    wsplit_kernel<<<224, 128>>>(c1W2, c2W2, c3W2, c2W1, c3W1);   // also zeroes g_pool
    edge1_mma_kernel<<<NPTS/32, 256, EDGE_SMEM_F>>>(c1W1, c1b1, c1b2, c2b1, abA);
    edge_mma_kernel<4,4,1><<<NPTS/64, 256, EDGE_SMEM_F>>>(abA, c2W1 + 128*64, c2b2, 1, 1, c3b1, abB);
    edge_mma_kernel<3,4,2><<<NPTS/64, 256, EDGE_SMEM_P>>>(abB, c3W1 + 128*64, c3b2, 2, 0, nullptr, nullptr);
    head_kernel<<<BGRAPH, 64>>>(regW, regb, out);
}